// round 2
// baseline (speedup 1.0000x reference)
#include <cuda_runtime.h>
#include <cstdint>

typedef unsigned long long u64;
typedef unsigned int u32;

#define BATCH 4
#define NPTS 32768
#define NPRE 4096
#define NPOST 512
#define NMS_T 0.7f

// ---------------- scratch (device globals; no allocation) ----------------
__device__ u64   g_keys [BATCH * NPTS];
__device__ float g_boxes[BATCH * NPRE * 7];
__device__ float g_x1[BATCH * NPRE], g_y1[BATCH * NPRE];
__device__ float g_x2[BATCH * NPRE], g_y2[BATCH * NPRE];
__device__ float g_ar[BATCH * NPRE];
__device__ float g_sc[BATCH * NPRE];
__device__ int   g_lb[BATCH * NPRE];
__device__ u64   g_mask[(size_t)BATCH * NPRE * 64];   // 8 MB

// ---------------- stage 1: build sort keys ----------------
__global__ void key_kernel(const float* __restrict__ cls) {
    int t = blockIdx.x * blockDim.x + threadIdx.x;
    if (t >= BATCH * NPTS) return;
    int n = t & (NPTS - 1);
    const float* c = cls + (size_t)t * 3;
    float c0 = c[0], c1 = c[1], c2 = c[2];
    float s = fmaxf(fmaxf(c0, c1), c2);
    u32 u = __float_as_uint(s);
    u32 enc = (u >> 31) ? ~u : (u ^ 0x80000000u);   // monotonic map
    g_keys[t] = ((u64)(~enc) << 32) | (u32)n;       // ascending => score desc, idx asc
}

// ---------------- stage 2: bitonic sort (per 32768-segment) ----------------
// Each block owns a contiguous 16384-key half-segment in 128 KB smem.
// Runs stages k in [k0, k1]; for k=32768 only the j<=8192 sub-steps (in-block).
__global__ void __launch_bounds__(1024, 1)
bitonic_smem_kernel(int k0, int k1) {
    extern __shared__ u64 s[];
    int half = blockIdx.x & 1;
    size_t base = (size_t)(blockIdx.x >> 1) * NPTS + (size_t)half * 16384;
    int halfBase = half * 16384;
    for (int t = threadIdx.x; t < 16384; t += 1024) s[t] = g_keys[base + t];
    __syncthreads();
    for (int k = k0; k <= k1; k <<= 1) {
        int jstart = (k >> 1) > 8192 ? 8192 : (k >> 1);
        for (int j = jstart; j >= 1; j >>= 1) {
            for (int p = threadIdx.x; p < 8192; p += 1024) {
                int i = (p & (j - 1)) | ((p & ~(j - 1)) << 1);
                bool up = (((halfBase + i) & k) == 0);
                u64 a = s[i], b = s[i + j];
                if ((a > b) == up) { s[i] = b; s[i + j] = a; }
            }
            __syncthreads();
        }
    }
    for (int t = threadIdx.x; t < 16384; t += 1024) g_keys[base + t] = s[t];
}

// global pass: k=32768, j=16384 (ascending everywhere within a segment)
__global__ void bitonic_global_kernel() {
    int p = blockIdx.x * blockDim.x + threadIdx.x;       // 4*16384 pairs
    if (p >= BATCH * 16384) return;
    int b = p >> 14, i = p & 16383;
    size_t lo = (size_t)b * NPTS + i, hi = lo + 16384;
    u64 a = g_keys[lo], c = g_keys[hi];
    if (a > c) { g_keys[lo] = c; g_keys[hi] = a; }
}

// ---------------- stage 3: gather top-4096, decompose boxes ----------------
__global__ void gather_kernel(const float* __restrict__ boxes,
                              const float* __restrict__ cls) {
    int t = blockIdx.x * blockDim.x + threadIdx.x;
    if (t >= BATCH * NPRE) return;
    int b = t >> 12;
    u64 key = g_keys[(size_t)b * NPTS + (t & (NPRE - 1))];
    int n = (u32)key;
    u32 enc = ~(u32)(key >> 32);
    u32 bits = (enc & 0x80000000u) ? (enc ^ 0x80000000u) : ~enc;
    g_sc[t] = __uint_as_float(bits);
    const float* bp = boxes + ((size_t)b * NPTS + n) * 7;
    float bx[7];
#pragma unroll
    for (int k = 0; k < 7; k++) { bx[k] = bp[k]; g_boxes[(size_t)t * 7 + k] = bx[k]; }
    float x = bx[0], y = bx[1], dx = bx[3], dy = bx[4];
    g_x1[t] = __fsub_rn(x, __fmul_rn(0.5f, dx));
    g_x2[t] = __fadd_rn(x, __fmul_rn(0.5f, dx));
    g_y1[t] = __fsub_rn(y, __fmul_rn(0.5f, dy));
    g_y2[t] = __fadd_rn(y, __fmul_rn(0.5f, dy));
    g_ar[t] = __fmul_rn(dx, dy);
    const float* c = cls + ((size_t)b * NPTS + n) * 3;
    float c0 = c[0], c1 = c[1], c2 = c[2];
    int l = 0; float m = c0;
    if (c1 > m) { m = c1; l = 1; }
    if (c2 > m) { l = 2; }
    g_lb[t] = l;
}

// ---------------- stage 4: IoU suppression bitmask ----------------
// grid: (64 colchunks, 16 rowblocks of 256 rows, 4 batches); upper triangle only.
__global__ void __launch_bounds__(256)
mask_kernel() {
    int c = blockIdx.x, b = blockIdx.z;
    int r0 = blockIdx.y * 256;
    if (c < (r0 >> 6)) return;                       // whole block below diagonal
    __shared__ float sx1[64], sy1[64], sx2[64], sy2[64], sa[64];
    int base = b * NPRE;
    if (threadIdx.x < 64) {
        int j = base + c * 64 + threadIdx.x;
        sx1[threadIdx.x] = g_x1[j]; sy1[threadIdx.x] = g_y1[j];
        sx2[threadIdx.x] = g_x2[j]; sy2[threadIdx.x] = g_y2[j];
        sa [threadIdx.x] = g_ar[j];
    }
    __syncthreads();
    int i = r0 + threadIdx.x;
    if (c < (i >> 6)) return;
    int gi = base + i;
    float x1 = g_x1[gi], y1 = g_y1[gi], x2 = g_x2[gi], y2 = g_y2[gi], ai = g_ar[gi];
    u64 w = 0;
#pragma unroll 8
    for (int k = 0; k < 64; k++) {
        float ix = fmaxf(0.0f, __fsub_rn(fminf(x2, sx2[k]), fmaxf(x1, sx1[k])));
        float iy = fmaxf(0.0f, __fsub_rn(fminf(y2, sy2[k]), fmaxf(y1, sy1[k])));
        float inter = __fmul_rn(ix, iy);
        // exactly: (area_i + area_j) - inter + 1e-6  (reference association order)
        float un = __fadd_rn(__fsub_rn(__fadd_rn(ai, sa[k]), inter), 1e-6f);
        float iou = __fdiv_rn(inter, un);
        if (iou > NMS_T) w |= (1ull << k);
    }
    g_mask[((size_t)b * NPRE + i) * 64 + c] = w;
}

// ---------------- stage 5: greedy scan + compaction + output ----------------
// One block per batch. Warp 0 scans (remv in registers, 2 words/lane);
// warps 1..7 double-buffer the next chunk's 64x64 mask words into smem.
__global__ void __launch_bounds__(256)
scan_kernel(float* __restrict__ out) {
    extern __shared__ u64 sm[];
    u64* buf   = sm;            // [2][64][64]
    u64* keepw = sm + 8192;     // [64]
    __shared__ unsigned pref[65];
    int b = blockIdx.x, tid = threadIdx.x, lane = tid & 31;
    const u64* M = g_mask + (size_t)b * NPRE * 64;

    // preload chunk 0
    for (int t = tid; t < 4096; t += 256) buf[t] = M[t];
    __syncthreads();

    u64 remv_lo = 0, remv_hi = 0;   // lane holds words `lane` and `lane+32`
    for (int c = 0; c < 64; c++) {
        const u64* B = buf + (size_t)(c & 1) * 4096;
        if (tid >= 32) {            // loaders: fetch chunk c+1
            if (c + 1 < 64) {
                u64* D = buf + (size_t)((c + 1) & 1) * 4096;
                const u64* S = M + (size_t)(c + 1) * 64 * 64;
                for (int t = tid - 32; t < 4096; t += 224) D[t] = S[t];
            }
        } else {                    // warp 0: scan chunk c
            u64 rl = __shfl_sync(0xFFFFFFFFu, remv_lo, c & 31);
            u64 rh = __shfl_sync(0xFFFFFFFFu, remv_hi, c & 31);
            u64 live = ~((c < 32) ? rl : rh);
            u64 kept = 0;
#pragma unroll 16
            for (int j = 0; j < 64; j++) {
                u64 m = B[j * 64 + c];          // broadcast LDS
                if ((live >> j) & 1) { kept |= (1ull << j); live &= ~m; }
            }
            u64 k2 = kept;
            while (k2) {
                int j = __ffsll((long long)k2) - 1;
                k2 &= k2 - 1;
                remv_lo |= B[j * 64 + lane];
                remv_hi |= B[j * 64 + lane + 32];
            }
            if (lane == 0) keepw[c] = kept;
        }
        __syncthreads();
    }

    if (tid == 0) {
        unsigned s = 0;
        for (int w = 0; w < 64; w++) { pref[w] = s; s += __popcll(keepw[w]); }
        pref[64] = s;
    }
    __syncthreads();

    float* rois = out;                               // [4,512,7]
    float* scor = out + BATCH * NPOST * 7;           // [4,512]
    float* labl = scor + BATCH * NPOST;              // [4,512]
    // zero-fill (empty slot label = 0 + 1 = 1)
    for (int p = tid; p < NPOST; p += 256) {
        float* r = rois + ((size_t)b * NPOST + p) * 7;
#pragma unroll
        for (int k = 0; k < 7; k++) r[k] = 0.0f;
        scor[b * NPOST + p] = 0.0f;
        labl[b * NPOST + p] = 1.0f;
    }
    __syncthreads();
    // scatter kept (rank < 512)
    for (int t = tid; t < NPRE; t += 256) {
        int cw = t >> 6, bp = t & 63;
        u64 kw = keepw[cw];
        if ((kw >> bp) & 1) {
            unsigned rank = pref[cw] + (unsigned)__popcll(kw & ((1ull << bp) - 1ull));
            if (rank < NPOST) {
                const float* src = g_boxes + ((size_t)b * NPRE + t) * 7;
                float* r = rois + ((size_t)b * NPOST + rank) * 7;
#pragma unroll
                for (int k = 0; k < 7; k++) r[k] = src[k];
                scor[b * NPOST + rank] = g_sc[b * NPRE + t];
                labl[b * NPOST + rank] = (float)(g_lb[b * NPRE + t] + 1);
            }
        }
    }
}

// ---------------- launch ----------------
extern "C" void kernel_launch(void* const* d_in, const int* in_sizes, int n_in,
                              void* d_out, int out_size) {
    const float* boxes = (const float*)d_in[0];
    const float* cls   = (const float*)d_in[1];
    float* out = (float*)d_out;

    cudaFuncSetAttribute(bitonic_smem_kernel,
                         cudaFuncAttributeMaxDynamicSharedMemorySize, 131072);
    cudaFuncSetAttribute(scan_kernel,
                         cudaFuncAttributeMaxDynamicSharedMemorySize, 2 * 4096 * 8 + 64 * 8);

    key_kernel<<<(BATCH * NPTS + 255) / 256, 256>>>(cls);
    bitonic_smem_kernel<<<8, 1024, 131072>>>(2, 16384);
    bitonic_global_kernel<<<(BATCH * 16384 + 255) / 256, 256>>>();
    bitonic_smem_kernel<<<8, 1024, 131072>>>(32768, 32768);
    gather_kernel<<<(BATCH * NPRE + 255) / 256, 256>>>(boxes, cls);
    {
        dim3 grid(64, 16, BATCH);
        mask_kernel<<<grid, 256>>>();
    }
    scan_kernel<<<BATCH, 256, 2 * 4096 * 8 + 64 * 8>>>(out);
}

// round 3
// speedup vs baseline: 1.2906x; 1.2906x over previous
#include <cuda_runtime.h>
#include <cstdint>

typedef unsigned long long u64;
typedef unsigned int u32;

#define BATCH 4
#define NPTS 32768
#define NPRE 4096
#define NPOST 512
#define NMS_T 0.7f

// ---------------- scratch (device globals; no allocation) ----------------
__device__ u64    g_keys [BATCH * NPTS];
__device__ float  g_boxes[BATCH * NPRE * 7];
__device__ float4 g_bb   [BATCH * NPRE];          // x1,y1,x2,y2
__device__ float  g_ar   [BATCH * NPRE];
__device__ float  g_sc   [BATCH * NPRE];
__device__ int    g_lb   [BATCH * NPRE];
__device__ u64    g_mask [(size_t)BATCH * NPRE * 64];   // 8 MB

// ---------------- stage 1: build keys + sort each 4096-segment ----------------
// 32 blocks: (batch, segment). Ascending u64 key = (~enc(score))<<32 | idx
// => ascending sort == score desc, index asc (matches top_k stability; no u64 ties).
__global__ void __launch_bounds__(512, 2)
segsort_kernel(const float* __restrict__ cls) {
    __shared__ u64 s[4096];
    int b   = blockIdx.x >> 3;
    int seg = blockIdx.x & 7;
    size_t base = (size_t)b * NPTS + (size_t)seg * 4096;
    for (int t = threadIdx.x; t < 4096; t += 512) {
        int n = seg * 4096 + t;
        const float* c = cls + ((size_t)b * NPTS + n) * 3;
        float c0 = c[0], c1 = c[1], c2 = c[2];
        float sc = fmaxf(fmaxf(c0, c1), c2);
        u32 u = __float_as_uint(sc);
        u32 enc = (u >> 31) ? ~u : (u ^ 0x80000000u);
        s[t] = ((u64)(~enc) << 32) | (u32)n;
    }
    __syncthreads();
    for (int k = 2; k <= 4096; k <<= 1) {
        for (int j = k >> 1; j >= 1; j >>= 1) {
            for (int p = threadIdx.x; p < 2048; p += 512) {
                int i = (p & (j - 1)) | ((p & ~(j - 1)) << 1);
                bool up = ((i & k) == 0);
                u64 a = s[i], bb = s[i + j];
                if ((a > bb) == up) { s[i] = bb; s[i + j] = a; }
            }
            __syncthreads();
        }
    }
    for (int t = threadIdx.x; t < 4096; t += 512) g_keys[base + t] = s[t];
}

// ---------------- stage 2: merge-select smallest 4096 of two sorted lists ----------------
// c[i] = min(a[i], b[4095-i]) is the 4096 smallest of a∪b and is bitonic;
// 12 ascending merge stages sort it. In-place at list a's location.
// final!=0: also gather boxes / scores / labels for the final top-4096.
__global__ void __launch_bounds__(512, 2)
merge_kernel(int nmerge, int stride, int final_pass,
             const float* __restrict__ boxes, const float* __restrict__ cls) {
    __shared__ u64 s[4096];
    int b = blockIdx.x / nmerge;
    int m = blockIdx.x % nmerge;
    size_t aoff = (size_t)b * NPTS + (size_t)m * 2 * stride * 4096;
    size_t boff = aoff + (size_t)stride * 4096;
    for (int t = threadIdx.x; t < 4096; t += 512) {
        u64 a = g_keys[aoff + t];
        u64 c = g_keys[boff + 4095 - t];
        s[t] = a < c ? a : c;
    }
    __syncthreads();
    for (int j = 2048; j >= 1; j >>= 1) {
        for (int p = threadIdx.x; p < 2048; p += 512) {
            int i = (p & (j - 1)) | ((p & ~(j - 1)) << 1);
            u64 a = s[i], c = s[i + j];
            if (a > c) { s[i] = c; s[i + j] = a; }
        }
        __syncthreads();
    }
    if (!final_pass) {
        for (int t = threadIdx.x; t < 4096; t += 512) g_keys[aoff + t] = s[t];
    } else {
        for (int t = threadIdx.x; t < 4096; t += 512) {
            u64 key = s[t];
            int n = (u32)key;
            u32 enc = ~(u32)(key >> 32);
            u32 bits = (enc & 0x80000000u) ? (enc ^ 0x80000000u) : ~enc;
            int o = b * NPRE + t;
            g_sc[o] = __uint_as_float(bits);
            const float* bp = boxes + ((size_t)b * NPTS + n) * 7;
            float bx[7];
#pragma unroll
            for (int k = 0; k < 7; k++) { bx[k] = bp[k]; g_boxes[(size_t)o * 7 + k] = bx[k]; }
            float x = bx[0], y = bx[1], dx = bx[3], dy = bx[4];
            float4 bb;
            bb.x = __fsub_rn(x, __fmul_rn(0.5f, dx));
            bb.y = __fsub_rn(y, __fmul_rn(0.5f, dy));
            bb.z = __fadd_rn(x, __fmul_rn(0.5f, dx));
            bb.w = __fadd_rn(y, __fmul_rn(0.5f, dy));
            g_bb[o] = bb;
            g_ar[o] = __fmul_rn(dx, dy);
            const float* c = cls + ((size_t)b * NPTS + n) * 3;
            float c0 = c[0], c1 = c[1], c2 = c[2];
            int l = 0; float mx = c0;
            if (c1 > mx) { mx = c1; l = 1; }
            if (c2 > mx) { l = 2; }
            g_lb[o] = l;
        }
    }
}

// ---------------- stage 3: IoU suppression bitmask ----------------
// grid: (64 colchunks, 16 rowblocks of 256 rows, 4 batches); upper triangle only.
// Division-free fast path; exact __fdiv_rn only within the ±1e-6 guard band.
__global__ void __launch_bounds__(256)
mask_kernel() {
    int c = blockIdx.x, b = blockIdx.z;
    int r0 = blockIdx.y * 256;
    if (c < (r0 >> 6)) return;
    __shared__ float4 sbb[64];
    __shared__ float  sa[64];
    int base = b * NPRE;
    if (threadIdx.x < 64) {
        int j = base + c * 64 + threadIdx.x;
        sbb[threadIdx.x] = g_bb[j];
        sa [threadIdx.x] = g_ar[j];
    }
    __syncthreads();
    int i = r0 + threadIdx.x;
    if (c < (i >> 6)) return;
    int gi = base + i;
    float4 bi = g_bb[gi];
    float ai = g_ar[gi];
    u64 w = 0;
#pragma unroll 8
    for (int k = 0; k < 64; k++) {
        float4 bj = sbb[k];
        float ix = fmaxf(0.0f, __fsub_rn(fminf(bi.z, bj.z), fmaxf(bi.x, bj.x)));
        float iy = fmaxf(0.0f, __fsub_rn(fminf(bi.w, bj.w), fmaxf(bi.y, bj.y)));
        float inter = __fmul_rn(ix, iy);
        // exactly: ((area_i + area_j) - inter) + 1e-6  (reference association order)
        float un = __fadd_rn(__fsub_rn(__fadd_rn(ai, sa[k]), inter), 1e-6f);
        float t  = __fmul_rn(NMS_T, un);
        bool sup;
        if (inter > __fmul_rn(t, 1.000001f))      sup = true;   // safely above threshold
        else if (inter < __fmul_rn(t, 0.999999f)) sup = false;  // safely below
        else sup = (__fdiv_rn(inter, un) > NMS_T);              // rare exact check
        if (sup) w |= (1ull << k);
    }
    g_mask[((size_t)b * NPRE + i) * 64 + c] = w;
}

// ---------------- stage 4: greedy scan + compaction + output ----------------
// One block per batch, 512 threads. Warp 0 scans (remv as ulonglong2 per lane);
// threads 32..511 double-buffer the next 64x64 mask chunk via uint4 loads.
__global__ void __launch_bounds__(512, 1)
scan_kernel(float* __restrict__ out) {
    extern __shared__ u64 sm[];
    u64* buf = sm;                      // [2][4096]
    __shared__ u64 keepw[64];
    __shared__ unsigned pref[65];
    int b = blockIdx.x, tid = threadIdx.x, lane = tid & 31;
    const u64* M = g_mask + (size_t)b * NPRE * 64;

    // preload chunk 0 (all threads, vectorized)
    {
        const uint4* S = (const uint4*)M;
        uint4* D = (uint4*)buf;
        for (int t = tid; t < 2048; t += 512) D[t] = S[t];
    }
    __syncthreads();

    ulonglong2 rv; rv.x = 0; rv.y = 0;   // lane holds remv words 2*lane, 2*lane+1
    for (int c = 0; c < 64; c++) {
        const u64* B = buf + (size_t)(c & 1) * 4096;
        if (tid >= 32) {                 // loaders: fetch chunk c+1
            if (c + 1 < 64) {
                uint4* D = (uint4*)(buf + (size_t)((c + 1) & 1) * 4096);
                const uint4* S = (const uint4*)(M + (size_t)(c + 1) * 4096);
#pragma unroll 5
                for (int t = tid - 32; t < 2048; t += 480) D[t] = S[t];
            }
        } else {                         // warp 0: scan chunk c
            u64 rw = __shfl_sync(0xFFFFFFFFu, (c & 1) ? rv.y : rv.x, c >> 1);
            u64 live = ~rw;
            u64 kept = 0;
#pragma unroll 16
            for (int j = 0; j < 64; j++) {
                u64 m = B[j * 64 + c];          // broadcast LDS
                if ((live >> j) & 1) { kept |= (1ull << j); live &= ~m; }
            }
            if (lane == 0) keepw[c] = kept;
            if (c < 63) {
                u64 k2 = kept;
                while (k2) {
                    int j = __ffsll((long long)k2) - 1;
                    k2 &= k2 - 1;
                    ulonglong2 m2 = *(const ulonglong2*)(B + j * 64 + 2 * lane);
                    rv.x |= m2.x; rv.y |= m2.y;
                }
            }
        }
        __syncthreads();
    }

    if (tid == 0) {
        unsigned s = 0;
        for (int w = 0; w < 64; w++) { pref[w] = s; s += __popcll(keepw[w]); }
        pref[64] = s;
    }
    __syncthreads();

    float* rois = out;                               // [4,512,7]
    float* scor = out + BATCH * NPOST * 7;           // [4,512]
    float* labl = scor + BATCH * NPOST;              // [4,512]
    // zero-fill (empty slot label = 0 + 1 = 1)
    for (int p = tid; p < NPOST; p += 512) {
        float* r = rois + ((size_t)b * NPOST + p) * 7;
#pragma unroll
        for (int k = 0; k < 7; k++) r[k] = 0.0f;
        scor[b * NPOST + p] = 0.0f;
        labl[b * NPOST + p] = 1.0f;
    }
    __syncthreads();
    // scatter kept (rank < 512)
    for (int t = tid; t < NPRE; t += 512) {
        int cw = t >> 6, bp = t & 63;
        u64 kw = keepw[cw];
        if ((kw >> bp) & 1) {
            unsigned rank = pref[cw] + (unsigned)__popcll(kw & ((1ull << bp) - 1ull));
            if (rank < NPOST) {
                const float* src = g_boxes + ((size_t)b * NPRE + t) * 7;
                float* r = rois + ((size_t)b * NPOST + rank) * 7;
#pragma unroll
                for (int k = 0; k < 7; k++) r[k] = src[k];
                scor[b * NPOST + rank] = g_sc[b * NPRE + t];
                labl[b * NPOST + rank] = (float)(g_lb[b * NPRE + t] + 1);
            }
        }
    }
}

// ---------------- launch ----------------
extern "C" void kernel_launch(void* const* d_in, const int* in_sizes, int n_in,
                              void* d_out, int out_size) {
    const float* boxes = (const float*)d_in[0];
    const float* cls   = (const float*)d_in[1];
    float* out = (float*)d_out;

    cudaFuncSetAttribute(scan_kernel,
                         cudaFuncAttributeMaxDynamicSharedMemorySize, 2 * 4096 * 8);

    segsort_kernel<<<32, 512>>>(cls);
    merge_kernel<<<16, 512>>>(4, 1, 0, boxes, cls);
    merge_kernel<<<8,  512>>>(2, 2, 0, boxes, cls);
    merge_kernel<<<4,  512>>>(1, 4, 1, boxes, cls);   // final: fused gather
    {
        dim3 grid(64, 16, BATCH);
        mask_kernel<<<grid, 256>>>();
    }
    scan_kernel<<<BATCH, 512, 2 * 4096 * 8>>>(out);
}

// round 4
// speedup vs baseline: 3.6946x; 2.8627x over previous
#include <cuda_runtime.h>
#include <cstdint>

typedef unsigned long long u64;
typedef unsigned int u32;

#define BATCH 4
#define NPTS 32768
#define NPRE 4096
#define NPOST 512

// ---------------- scratch ----------------
__device__ u64 g_keys[BATCH * NPTS];

// ---------------- stage 1: build keys + sort each 4096-segment ----------------
// 32 blocks: (batch, segment). Ascending u64 key = (~enc(score))<<32 | idx
// => ascending sort == score desc, index asc (matches top_k stability; keys unique).
__global__ void __launch_bounds__(1024, 1)
segsort_kernel(const float* __restrict__ cls) {
    __shared__ u64 s[4096];
    int b   = blockIdx.x >> 3;
    int seg = blockIdx.x & 7;
    size_t base = (size_t)b * NPTS + (size_t)seg * 4096;
    for (int t = threadIdx.x; t < 4096; t += 1024) {
        int n = seg * 4096 + t;
        const float* c = cls + ((size_t)b * NPTS + n) * 3;
        float c0 = c[0], c1 = c[1], c2 = c[2];
        float sc = fmaxf(fmaxf(c0, c1), c2);
        u32 u = __float_as_uint(sc);
        u32 enc = (u >> 31) ? ~u : (u ^ 0x80000000u);
        s[t] = ((u64)(~enc) << 32) | (u32)n;
    }
    __syncthreads();
    for (int k = 2; k <= 4096; k <<= 1) {
        for (int j = k >> 1; j >= 1; j >>= 1) {
            for (int p = threadIdx.x; p < 2048; p += 1024) {
                int i = (p & (j - 1)) | ((p & ~(j - 1)) << 1);
                bool up = ((i & k) == 0);
                u64 a = s[i], bb = s[i + j];
                if ((a > bb) == up) { s[i] = bb; s[i + j] = a; }
            }
            __syncthreads();
        }
    }
    for (int t = threadIdx.x; t < 4096; t += 1024) g_keys[base + t] = s[t];
}

// ---------------- stage 2: merge-select smallest 4096 of two sorted 4096-lists ----------------
// c[i] = min(a[i], b[4095-i]) is the 4096 smallest of a∪b and is bitonic;
// 12 ascending stages sort it. In-place at list a's location.
__global__ void __launch_bounds__(512, 2)
merge_kernel(int nmerge, int stride) {
    __shared__ u64 s[4096];
    int b = blockIdx.x / nmerge;
    int m = blockIdx.x % nmerge;
    size_t aoff = (size_t)b * NPTS + (size_t)m * 2 * stride * 4096;
    size_t boff = aoff + (size_t)stride * 4096;
    for (int t = threadIdx.x; t < 4096; t += 512) {
        u64 a = g_keys[aoff + t];
        u64 c = g_keys[boff + 4095 - t];
        s[t] = a < c ? a : c;
    }
    __syncthreads();
    for (int j = 2048; j >= 1; j >>= 1) {
        for (int p = threadIdx.x; p < 2048; p += 512) {
            int i = (p & (j - 1)) | ((p & ~(j - 1)) << 1);
            u64 a = s[i], c = s[i + j];
            if (a > c) { s[i] = c; s[i + j] = a; }
        }
        __syncthreads();
    }
    for (int t = threadIdx.x; t < 4096; t += 512) g_keys[aoff + t] = s[t];
}

// ---------------- stage 3: fused lazy NMS + output (one block per batch) ----------------
// Exploits: output depends only on keeps up to rank 511 -> stop there.
__global__ void __launch_bounds__(1024, 1)
nms_kernel(const float* __restrict__ boxes, const float* __restrict__ cls,
           float* __restrict__ out) {
    extern __shared__ char sm[];
    float4* bb = (float4*)sm;                       // [4096] 64KB
    float*  ar = (float*)(bb + NPRE);               // [4096] 16KB
    __shared__ u32 diag32[128];                     // 64 x u64 as 2xu32
    __shared__ u32 supArr[64];
    __shared__ u32 keptIdx[NPOST];
    __shared__ u32 ballots[2];
    __shared__ int keptCount;

    int b = blockIdx.x, tid = threadIdx.x;
    const u64* keys = g_keys + (size_t)b * NPTS;    // first 4096 = sorted top-4096

    // gather box bounds/areas for top-4096 into smem
    for (int t = tid; t < NPRE; t += 1024) {
        u64 key = keys[t];
        int n = (u32)key;
        const float* bp = boxes + ((size_t)b * NPTS + n) * 7;
        float x = bp[0], y = bp[1], dx = bp[3], dy = bp[4];
        float4 v;
        v.x = __fsub_rn(x, __fmul_rn(0.5f, dx));
        v.y = __fsub_rn(y, __fmul_rn(0.5f, dy));
        v.z = __fadd_rn(x, __fmul_rn(0.5f, dx));
        v.w = __fadd_rn(y, __fmul_rn(0.5f, dy));
        bb[t] = v;
        ar[t] = __fmul_rn(dx, dy);
    }
    if (tid == 0) keptCount = 0;
    __syncthreads();

    for (int c = 0; c < 64; c++) {
        if (tid < 64) supArr[tid] = 0;
        __syncthreads();
        // (a) suppression of chunk boxes by global kept list (16 kept-slots x 64 boxes)
        {
            int il = tid & 63, ks = tid >> 6;
            int gi = c * 64 + il;
            float4 bi = bb[gi]; float ai = ar[gi];
            int kc = keptCount;
            bool s = false;
            for (int kt = ks; kt < kc; kt += 16) {
                int k = keptIdx[kt];
                float4 bj = bb[k]; float aj = ar[k];
                float ix = fmaxf(0.0f, __fsub_rn(fminf(bi.z, bj.z), fmaxf(bi.x, bj.x)));
                float iy = fmaxf(0.0f, __fsub_rn(fminf(bi.w, bj.w), fmaxf(bi.y, bj.y)));
                float inter = __fmul_rn(ix, iy);
                float un = __fadd_rn(__fsub_rn(__fadd_rn(aj, ai), inter), 1e-6f);
                if (__fdiv_rn(inter, un) > 0.7f) { s = true; break; }
            }
            if (s) atomicOr(&supArr[il], 1u);
        }
        // (b) diagonal masks: diag[i] = bits j>i (within chunk) suppressed by i
        {
            int lane = tid & 31;
#pragma unroll
            for (int pass = 0; pass < 4; pass++) {
                int i = pass * 16 + (tid >> 6);
                int j = tid & 63;
                bool p = false;
                if (j > i) {
                    int gi = c * 64 + i, gj = c * 64 + j;
                    float4 bi = bb[gi], bj = bb[gj];
                    float ix = fmaxf(0.0f, __fsub_rn(fminf(bi.z, bj.z), fmaxf(bi.x, bj.x)));
                    float iy = fmaxf(0.0f, __fsub_rn(fminf(bi.w, bj.w), fmaxf(bi.y, bj.y)));
                    float inter = __fmul_rn(ix, iy);
                    float un = __fadd_rn(__fsub_rn(__fadd_rn(ar[gi], ar[gj]), inter), 1e-6f);
                    p = __fdiv_rn(inter, un) > 0.7f;
                }
                u32 bal = __ballot_sync(0xFFFFFFFFu, p);
                if (lane == 0) diag32[i * 2 + ((tid >> 5) & 1)] = bal;
            }
        }
        __syncthreads();
        if (tid < 64) {
            u32 bal = __ballot_sync(0xFFFFFFFFu, supArr[tid] != 0);
            if ((tid & 31) == 0) ballots[tid >> 5] = bal;
        }
        __syncthreads();
        // (c) serial greedy within chunk
        if (tid == 0) {
            u64 live = ~(((u64)ballots[1] << 32) | (u64)ballots[0]);
            int kc = keptCount;
            for (int j = 0; j < 64 && kc < NPOST; j++) {
                if ((live >> j) & 1) {
                    keptIdx[kc++] = c * 64 + j;
                    u64 w = ((u64)diag32[j * 2 + 1] << 32) | (u64)diag32[j * 2];
                    live &= ~w;
                }
            }
            keptCount = kc;
        }
        __syncthreads();
        if (keptCount >= NPOST) break;
    }

    // output
    float* rois = out;                               // [4,512,7]
    float* scor = out + BATCH * NPOST * 7;           // [4,512]
    float* labl = scor + BATCH * NPOST;              // [4,512]
    int kc = keptCount;
    for (int r = tid; r < NPOST; r += 1024) {
        float bx[7] = {0, 0, 0, 0, 0, 0, 0};
        float sc = 0.0f, lb = 1.0f;                  // empty: label 0+1
        if (r < kc) {
            u64 key = keys[keptIdx[r]];
            int n = (u32)key;
            u32 enc = ~(u32)(key >> 32);
            u32 sbits = (enc & 0x80000000u) ? (enc ^ 0x80000000u) : ~enc;
            sc = __uint_as_float(sbits);
            const float* bp = boxes + ((size_t)b * NPTS + n) * 7;
#pragma unroll
            for (int k = 0; k < 7; k++) bx[k] = bp[k];
            const float* cp = cls + ((size_t)b * NPTS + n) * 3;
            float c0 = cp[0], c1 = cp[1], c2 = cp[2];
            int l = 0; float m = c0;
            if (c1 > m) { m = c1; l = 1; }
            if (c2 > m) { l = 2; }
            lb = (float)(l + 1);
        }
        float* rp = rois + ((size_t)b * NPOST + r) * 7;
#pragma unroll
        for (int k = 0; k < 7; k++) rp[k] = bx[k];
        scor[b * NPOST + r] = sc;
        labl[b * NPOST + r] = lb;
    }
}

// ---------------- launch ----------------
extern "C" void kernel_launch(void* const* d_in, const int* in_sizes, int n_in,
                              void* d_out, int out_size) {
    const float* boxes = (const float*)d_in[0];
    const float* cls   = (const float*)d_in[1];
    float* out = (float*)d_out;

    int nms_smem = NPRE * sizeof(float4) + NPRE * sizeof(float);   // 80KB
    cudaFuncSetAttribute(nms_kernel,
                         cudaFuncAttributeMaxDynamicSharedMemorySize, nms_smem);

    segsort_kernel<<<32, 1024>>>(cls);
    merge_kernel<<<16, 512>>>(4, 1);
    merge_kernel<<<8,  512>>>(2, 2);
    merge_kernel<<<4,  512>>>(1, 4);
    nms_kernel<<<BATCH, 1024, nms_smem>>>(boxes, cls, out);
}

// round 6
// speedup vs baseline: 4.9300x; 1.3344x over previous
#include <cuda_runtime.h>
#include <cstdint>

typedef unsigned long long u64;
typedef unsigned int u32;

#define BATCH 4
#define NPTS 32768
#define NPRE 4096
#define NPOST 512

// ---------------- scratch ----------------
__device__ u64 g_keys[BATCH * NPTS];

// ---------------- bitonic helpers ----------------
__device__ __forceinline__ void cswap(u64& a, u64& b, bool up) {
    u64 lo = a < b ? a : b;
    u64 hi = a < b ? b : a;
    a = up ? lo : hi;
    b = up ? hi : lo;
}

// Register/shfl substeps j = jtop..1 for bitonic stage k (jtop <= 64).
// Thread t owns elements [4t, 4t+4). Direction up = ((i & k) == 0) is constant
// over a thread's 4 elements and over shfl partners (bit(j) < bit(k)).
__device__ __forceinline__ void reg_phase(u64 e[4], int t, int k, int jtop) {
    bool up = ((t & (k >> 2)) == 0);
    for (int j = jtop; j >= 4; j >>= 1) {
        int d = j >> 2;
        bool keepLow = (((t & d) == 0) == up);
#pragma unroll
        for (int m = 0; m < 4; m++) {
            u64 p = __shfl_xor_sync(0xFFFFFFFFu, e[m], d);
            u64 lo = e[m] < p ? e[m] : p;
            u64 hi = e[m] < p ? p : e[m];
            e[m] = keepLow ? lo : hi;
        }
    }
    cswap(e[0], e[2], up); cswap(e[1], e[3], up);   // j = 2
    cswap(e[0], e[1], up); cswap(e[2], e[3], up);   // j = 1
}

// ---------------- stage 1: build keys + sort each 4096-segment ----------------
// Ascending u64 key = (~enc(score))<<32 | idx  => score desc, index asc (top_k stable).
__global__ void __launch_bounds__(1024, 1)
segsort_kernel(const float* __restrict__ cls) {
    __shared__ u64 s[4096];
    int b = blockIdx.x >> 3, seg = blockIdx.x & 7;
    size_t base = (size_t)b * NPTS + (size_t)seg * 4096;
    int t = threadIdx.x;
    u64 e[4];
#pragma unroll
    for (int m = 0; m < 4; m++) {
        int i = 4 * t + m;
        int n = seg * 4096 + i;
        const float* c = cls + ((size_t)b * NPTS + n) * 3;
        float c0 = c[0], c1 = c[1], c2 = c[2];
        float sc = fmaxf(fmaxf(c0, c1), c2);
        u32 u = __float_as_uint(sc);
        u32 enc = (u >> 31) ? ~u : (u ^ 0x80000000u);
        e[m] = ((u64)(~enc) << 32) | (u32)n;
    }
    // k = 2 : up for pair (4t,4t+1), down for (4t+2,4t+3)
    cswap(e[0], e[1], true); cswap(e[2], e[3], false);
    // k = 4..128 : entirely in registers/shuffles, no barriers
    for (int k = 4; k <= 128; k <<= 1)
        reg_phase(e, t, k, (k >> 1) < 64 ? (k >> 1) : 64);
    // k = 256..4096 : smem for j >= 128, then registers
    for (int k = 256; k <= 4096; k <<= 1) {
#pragma unroll
        for (int m = 0; m < 4; m++) s[4 * t + m] = e[m];
        __syncthreads();
        for (int j = k >> 1; j >= 128; j >>= 1) {
#pragma unroll
            for (int h = 0; h < 2; h++) {
                int p = t + h * 1024;
                int i = (p & (j - 1)) | ((p & ~(j - 1)) << 1);
                bool up = ((i & k) == 0);
                u64 A = s[i], B = s[i + j];
                if ((A > B) == up) { s[i] = B; s[i + j] = A; }
            }
            __syncthreads();
        }
#pragma unroll
        for (int m = 0; m < 4; m++) e[m] = s[4 * t + m];
        reg_phase(e, t, k, 64);
    }
#pragma unroll
    for (int m = 0; m < 4; m++) g_keys[base + 4 * t + m] = e[m];
}

// ---------------- stage 2: merge-select smallest 4096 of two sorted 4096-lists ----
// c[i] = min(a[i], b[4095-i]) is bitonic and holds the 4096 smallest of the union;
// ascending cleanup: smem j=2048..128, then shfl/register j=64..1.
__global__ void __launch_bounds__(1024, 1)
merge_kernel(int nmerge, int stride) {
    __shared__ u64 s[4096];
    int b = blockIdx.x / nmerge, m = blockIdx.x % nmerge;
    size_t aoff = (size_t)b * NPTS + (size_t)m * 2 * stride * 4096;
    size_t boff = aoff + (size_t)stride * 4096;
    int t = threadIdx.x;
#pragma unroll
    for (int q = 0; q < 4; q++) {
        int i = 4 * t + q;
        u64 a = g_keys[aoff + i];
        u64 c = g_keys[boff + 4095 - i];
        s[i] = a < c ? a : c;
    }
    __syncthreads();
    for (int j = 2048; j >= 128; j >>= 1) {
#pragma unroll
        for (int h = 0; h < 2; h++) {
            int p = t + h * 1024;
            int i = (p & (j - 1)) | ((p & ~(j - 1)) << 1);
            u64 A = s[i], B = s[i + j];
            if (A > B) { s[i] = B; s[i + j] = A; }
        }
        __syncthreads();
    }
    u64 e[4];
#pragma unroll
    for (int q = 0; q < 4; q++) e[q] = s[4 * t + q];
    for (int j = 64; j >= 4; j >>= 1) {
        int d = j >> 2;
        bool keepLow = ((t & d) == 0);
#pragma unroll
        for (int q = 0; q < 4; q++) {
            u64 p = __shfl_xor_sync(0xFFFFFFFFu, e[q], d);
            u64 lo = e[q] < p ? e[q] : p;
            u64 hi = e[q] < p ? p : e[q];
            e[q] = keepLow ? lo : hi;
        }
    }
    cswap(e[0], e[2], true); cswap(e[1], e[3], true);
    cswap(e[0], e[1], true); cswap(e[2], e[3], true);
#pragma unroll
    for (int q = 0; q < 4; q++) g_keys[aoff + 4 * t + q] = e[q];
}

// ---------------- IoU suppression test (guard-banded, division-free fast path) ----
__device__ __forceinline__ bool iou_sup(float4 bi, float ai, float4 bj, float aj) {
    float ix = fmaxf(0.0f, __fsub_rn(fminf(bi.z, bj.z), fmaxf(bi.x, bj.x)));
    float iy = fmaxf(0.0f, __fsub_rn(fminf(bi.w, bj.w), fmaxf(bi.y, bj.y)));
    float inter = __fmul_rn(ix, iy);
    // exactly: ((area_i + area_j) - inter) + 1e-6  (reference association order)
    float un = __fadd_rn(__fsub_rn(__fadd_rn(ai, aj), inter), 1e-6f);
    float thr = __fmul_rn(0.7f, un);
    if (inter > __fmul_rn(thr, 1.000001f)) return true;
    if (inter < __fmul_rn(thr, 0.999999f)) return false;
    return __fdiv_rn(inter, un) > 0.7f;            // rare exact check
}

// ---------------- stage 3: fused lazy NMS + output (one block per batch) --------
// Output depends only on keeps up to rank 511 -> stop there; gather boxes lazily.
__global__ void __launch_bounds__(1024, 1)
nms_kernel(const float* __restrict__ boxes, const float* __restrict__ cls,
           float* __restrict__ out) {
    __shared__ float  raw[64][8];
    __shared__ float4 bbChunk[64];
    __shared__ float  arChunk[64];
    __shared__ float4 keptBB[NPOST];
    __shared__ float  keptAr[NPOST];
    __shared__ u32    keptIdx[NPOST];
    __shared__ u32    chunkN[64];
    __shared__ u32    diag32[128];
    __shared__ u32    supArr[64];
    __shared__ u32    ballots[2];
    __shared__ int    keptCount, prevCount;

    int b = blockIdx.x, tid = threadIdx.x;
    const u64* keys = g_keys + (size_t)b * NPTS;   // first 4096 = sorted top-4096
    if (tid == 0) keptCount = 0;
    __syncthreads();

    for (int c = 0; c < 64; c++) {
        if (tid < 64) {
            chunkN[tid] = (u32)keys[c * 64 + tid];
            supArr[tid] = 0;
        }
        __syncthreads();
        if (tid < 512) {                            // lazy gather of this chunk's boxes
            int l = tid >> 3, comp = tid & 7;
            if (comp < 7)
                raw[l][comp] = boxes[((size_t)b * NPTS + chunkN[l]) * 7 + comp];
        }
        __syncthreads();
        if (tid < 64) {
            float x = raw[tid][0], y = raw[tid][1], dx = raw[tid][3], dy = raw[tid][4];
            float4 v;
            v.x = __fsub_rn(x, __fmul_rn(0.5f, dx));
            v.y = __fsub_rn(y, __fmul_rn(0.5f, dy));
            v.z = __fadd_rn(x, __fmul_rn(0.5f, dx));
            v.w = __fadd_rn(y, __fmul_rn(0.5f, dy));
            bbChunk[tid] = v;
            arChunk[tid] = __fmul_rn(dx, dy);
        }
        __syncthreads();
        // (a) suppression of chunk boxes by global kept list (16 slots x 64 boxes)
        {
            int il = tid & 63, ks = tid >> 6;
            float4 bi = bbChunk[il]; float ai = arChunk[il];
            int kc = keptCount;
            bool sres = false;
            for (int kt = ks; kt < kc; kt += 16) {
                if (iou_sup(keptBB[kt], keptAr[kt], bi, ai)) { sres = true; break; }
            }
            if (sres) atomicOr(&supArr[il], 1u);
        }
        // (b) diagonal masks: diag[i] = bits j>i (within chunk) suppressed by i
        {
            int lane = tid & 31;
#pragma unroll
            for (int pass = 0; pass < 4; pass++) {
                int i = pass * 16 + (tid >> 6);
                int j = tid & 63;
                bool p = false;
                if (j > i)
                    p = iou_sup(bbChunk[i], arChunk[i], bbChunk[j], arChunk[j]);
                u32 bal = __ballot_sync(0xFFFFFFFFu, p);
                if (lane == 0) diag32[i * 2 + ((tid >> 5) & 1)] = bal;
            }
        }
        __syncthreads();
        if (tid < 64) {
            u32 bal = __ballot_sync(0xFFFFFFFFu, supArr[tid] != 0);
            if ((tid & 31) == 0) ballots[tid >> 5] = bal;
        }
        __syncthreads();
        // (c) serial greedy within chunk
        if (tid == 0) {
            prevCount = keptCount;
            u64 live = ~(((u64)ballots[1] << 32) | (u64)ballots[0]);
            int kc = keptCount;
            for (int j = 0; j < 64 && kc < NPOST; j++) {
                if ((live >> j) & 1) {
                    keptIdx[kc++] = c * 64 + j;
                    u64 w = ((u64)diag32[j * 2 + 1] << 32) | (u64)diag32[j * 2];
                    live &= ~w;
                }
            }
            keptCount = kc;
        }
        __syncthreads();
        {   // append new kept boxes to compact list
            int r = prevCount + tid;
            if (r < keptCount) {
                int slot = keptIdx[r] & 63;
                keptBB[r] = bbChunk[slot];
                keptAr[r] = arChunk[slot];
            }
        }
        __syncthreads();
        if (keptCount >= NPOST) break;
    }

    // output
    float* rois = out;                               // [4,512,7]
    float* scor = out + BATCH * NPOST * 7;           // [4,512]
    float* labl = scor + BATCH * NPOST;              // [4,512]
    int kc = keptCount;
    for (int r = tid; r < NPOST; r += 1024) {
        float bx[7] = {0, 0, 0, 0, 0, 0, 0};
        float sc = 0.0f, lb = 1.0f;                  // empty: label 0+1
        if (r < kc) {
            u64 key = keys[keptIdx[r]];
            int n = (u32)key;
            u32 enc = ~(u32)(key >> 32);
            u32 sbits = (enc & 0x80000000u) ? (enc ^ 0x80000000u) : ~enc;
            sc = __uint_as_float(sbits);
            const float* bp = boxes + ((size_t)b * NPTS + n) * 7;
#pragma unroll
            for (int k = 0; k < 7; k++) bx[k] = bp[k];
            const float* cp = cls + ((size_t)b * NPTS + n) * 3;
            float c0 = cp[0], c1 = cp[1], c2 = cp[2];
            int l = 0; float m = c0;
            if (c1 > m) { m = c1; l = 1; }
            if (c2 > m) { l = 2; }
            lb = (float)(l + 1);
        }
        float* rp = rois + ((size_t)b * NPOST + r) * 7;
#pragma unroll
        for (int k = 0; k < 7; k++) rp[k] = bx[k];
        scor[b * NPOST + r] = sc;
        labl[b * NPOST + r] = lb;
    }
}

// ---------------- launch ----------------
extern "C" void kernel_launch(void* const* d_in, const int* in_sizes, int n_in,
                              void* d_out, int out_size) {
    const float* boxes = (const float*)d_in[0];
    const float* cls   = (const float*)d_in[1];
    float* out = (float*)d_out;

    segsort_kernel<<<32, 1024>>>(cls);
    merge_kernel<<<16, 1024>>>(4, 1);
    merge_kernel<<<8,  1024>>>(2, 2);
    merge_kernel<<<4,  1024>>>(1, 4);
    nms_kernel<<<BATCH, 1024>>>(boxes, cls, out);
}

// round 14
// speedup vs baseline: 4.9858x; 1.0113x over previous
#include <cuda_runtime.h>
#include <cstdint>

typedef unsigned long long u64;
typedef unsigned int u32;

#define BATCH 4
#define NPTS 32768
#define NPRE 4096
#define NPOST 512

// ---------------- scratch ----------------
__device__ u64 g_keys[BATCH * NPTS];

// ---------------- bitonic helpers ----------------
__device__ __forceinline__ void cswap(u64& a, u64& b, bool up) {
    u64 lo = a < b ? a : b;
    u64 hi = a < b ? b : a;
    a = up ? lo : hi;
    b = up ? hi : lo;
}

// Register/shfl substeps j = jtop..1 for bitonic stage k (jtop <= 64).
// Thread t owns elements [4t, 4t+4). Direction up = ((i & k) == 0) is constant
// over a thread's 4 elements and over shfl partners (bit(j) < bit(k)).
__device__ __forceinline__ void reg_phase(u64 e[4], int t, int k, int jtop) {
    bool up = ((t & (k >> 2)) == 0);
    for (int j = jtop; j >= 4; j >>= 1) {
        int d = j >> 2;
        bool keepLow = (((t & d) == 0) == up);
#pragma unroll
        for (int m = 0; m < 4; m++) {
            u64 p = __shfl_xor_sync(0xFFFFFFFFu, e[m], d);
            u64 lo = e[m] < p ? e[m] : p;
            u64 hi = e[m] < p ? p : e[m];
            e[m] = keepLow ? lo : hi;
        }
    }
    cswap(e[0], e[2], up); cswap(e[1], e[3], up);   // j = 2
    cswap(e[0], e[1], up); cswap(e[2], e[3], up);   // j = 1
}

// ---------------- stage 1: build keys + sort each 4096-segment ----------------
// Ascending u64 key = (~enc(score))<<32 | idx  => score desc, index asc (top_k stable).
__global__ void __launch_bounds__(1024, 1)
segsort_kernel(const float* __restrict__ cls) {
    __shared__ u64 s[4096];
    int b = blockIdx.x >> 3, seg = blockIdx.x & 7;
    size_t base = (size_t)b * NPTS + (size_t)seg * 4096;
    int t = threadIdx.x;
    u64 e[4];
    {   // vectorized key build: 12 consecutive floats = 3 x float4 per thread
        const float4* cp4 = (const float4*)(cls + base * 3);
        float4 A = cp4[3 * t], B = cp4[3 * t + 1], C = cp4[3 * t + 2];
        float scs[4];
        scs[0] = fmaxf(fmaxf(A.x, A.y), A.z);
        scs[1] = fmaxf(fmaxf(A.w, B.x), B.y);
        scs[2] = fmaxf(fmaxf(B.z, B.w), C.x);
        scs[3] = fmaxf(fmaxf(C.y, C.z), C.w);
#pragma unroll
        for (int m = 0; m < 4; m++) {
            u32 u = __float_as_uint(scs[m]);
            u32 enc = (u >> 31) ? ~u : (u ^ 0x80000000u);
            e[m] = ((u64)(~enc) << 32) | (u32)(seg * 4096 + 4 * t + m);
        }
    }
    // k = 2 : up for pair (4t,4t+1), down for (4t+2,4t+3)
    cswap(e[0], e[1], true); cswap(e[2], e[3], false);
    // k = 4..128 : entirely in registers/shuffles, no barriers
    for (int k = 4; k <= 128; k <<= 1)
        reg_phase(e, t, k, (k >> 1) < 64 ? (k >> 1) : 64);
    // k = 256..4096 : smem for j >= 128, then registers
    for (int k = 256; k <= 4096; k <<= 1) {
#pragma unroll
        for (int m = 0; m < 4; m++) s[4 * t + m] = e[m];
        __syncthreads();
        for (int j = k >> 1; j >= 128; j >>= 1) {
#pragma unroll
            for (int h = 0; h < 2; h++) {
                int p = t + h * 1024;
                int i = (p & (j - 1)) | ((p & ~(j - 1)) << 1);
                bool up = ((i & k) == 0);
                u64 A = s[i], B = s[i + j];
                if ((A > B) == up) { s[i] = B; s[i + j] = A; }
            }
            __syncthreads();
        }
#pragma unroll
        for (int m = 0; m < 4; m++) e[m] = s[4 * t + m];
        reg_phase(e, t, k, 64);
    }
#pragma unroll
    for (int m = 0; m < 4; m++) g_keys[base + 4 * t + m] = e[m];
}

// ---------------- IoU suppression test (guard-banded, division-free fast path) ----
__device__ __forceinline__ bool iou_sup(float4 bi, float ai, float4 bj, float aj) {
    float ix = fmaxf(0.0f, __fsub_rn(fminf(bi.z, bj.z), fmaxf(bi.x, bj.x)));
    float iy = fmaxf(0.0f, __fsub_rn(fminf(bi.w, bj.w), fmaxf(bi.y, bj.y)));
    float inter = __fmul_rn(ix, iy);
    // exactly: ((area_i + area_j) - inter) + 1e-6  (reference association order)
    float un = __fadd_rn(__fsub_rn(__fadd_rn(ai, aj), inter), 1e-6f);
    float thr = __fmul_rn(0.7f, un);
    if (inter > __fmul_rn(thr, 1.000001f)) return true;
    if (inter < __fmul_rn(thr, 0.999999f)) return false;
    return __fdiv_rn(inter, un) > 0.7f;            // rare exact check
}

// ---------------- stage 2: fused merge-select + lazy NMS + output --------------
// One block per batch. 7 sequential merge-select rounds fold the 8 sorted
// segments into the exact sorted top-4096 (in smem); then lazy chunked NMS with
// double-buffered box prefetch, early exit at 512 keeps.
__global__ void __launch_bounds__(1024, 1)
fused_kernel(const float* __restrict__ boxes, const float* __restrict__ cls,
             float* __restrict__ out) {
    extern __shared__ u64 s[];                      // [4096] keys, 32 KB dynamic
    __shared__ float  raw[2][64][8];
    __shared__ float4 bbChunk[64];
    __shared__ float  arChunk[64];
    __shared__ float4 keptBB[NPOST];
    __shared__ float  keptAr[NPOST];
    __shared__ u32    keptIdx[NPOST];
    __shared__ u32    diag32[128];
    __shared__ u32    supArr[64];
    __shared__ u32    ballots[2];
    __shared__ int    keptCount, prevCount;

    int b = blockIdx.x, t = threadIdx.x;
    size_t segbase = (size_t)b * NPTS;

    // ---- merge-select: fold segments 1..7 into register-resident R (= seg 0) ----
    u64 e[4], bv[4];
#pragma unroll
    for (int m = 0; m < 4; m++) e[m]  = g_keys[segbase + 4 * t + m];
#pragma unroll
    for (int m = 0; m < 4; m++) bv[m] = g_keys[segbase + 4096 + 4095 - (4 * t + m)];
    for (int r = 1; r < 8; r++) {
        // c[i] = min(R[i], seg_r[4095-i]) : bitonic, holds smallest 4096 of union
#pragma unroll
        for (int m = 0; m < 4; m++) { u64 x = bv[m]; e[m] = e[m] < x ? e[m] : x; }
#pragma unroll
        for (int m = 0; m < 4; m++) s[4 * t + m] = e[m];
        __syncthreads();
        if (r < 7) {                                // prefetch next segment (reversed)
#pragma unroll
            for (int m = 0; m < 4; m++)
                bv[m] = g_keys[segbase + (size_t)(r + 1) * 4096 + 4095 - (4 * t + m)];
        }
        for (int j = 2048; j >= 128; j >>= 1) {     // ascending cleanup, smem part
#pragma unroll
            for (int h = 0; h < 2; h++) {
                int p = t + h * 1024;
                int i = (p & (j - 1)) | ((p & ~(j - 1)) << 1);
                u64 A = s[i], B = s[i + j];
                if (A > B) { s[i] = B; s[i + j] = A; }
            }
            __syncthreads();
        }
#pragma unroll
        for (int m = 0; m < 4; m++) e[m] = s[4 * t + m];
        for (int j = 64; j >= 4; j >>= 1) {         // ascending cleanup, shfl part
            int d = j >> 2;
            bool keepLow = ((t & d) == 0);
#pragma unroll
            for (int m = 0; m < 4; m++) {
                u64 p = __shfl_xor_sync(0xFFFFFFFFu, e[m], d);
                u64 lo = e[m] < p ? e[m] : p;
                u64 hi = e[m] < p ? p : e[m];
                e[m] = keepLow ? lo : hi;
            }
        }
        cswap(e[0], e[2], true); cswap(e[1], e[3], true);
        cswap(e[0], e[1], true); cswap(e[2], e[3], true);
    }
#pragma unroll
    for (int m = 0; m < 4; m++) s[4 * t + m] = e[m];   // final sorted top-4096
    if (t == 0) keptCount = 0;
    __syncthreads();

    // ---- lazy NMS over 64-box chunks, double-buffered box gather ----
    if (t < 512) {                                  // prefetch chunk 0
        int l = t >> 3, comp = t & 7;
        if (comp < 7) {
            int n = (u32)s[l];
            raw[0][l][comp] = boxes[((size_t)b * NPTS + n) * 7 + comp];
        }
    }
    __syncthreads();

    for (int c = 0; c < 64; c++) {
        // issue next chunk's scattered loads now; commit to smem at chunk end
        float pf = 0.0f;
        int pl = t >> 3, pcomp = t & 7;
        bool doPf = (t < 512) && (pcomp < 7) && (c + 1 < 64);
        if (doPf) {
            int n = (u32)s[(c + 1) * 64 + pl];
            pf = boxes[((size_t)b * NPTS + n) * 7 + pcomp];
        }
        if (t < 64) {
            supArr[t] = 0;
            float x = raw[c & 1][t][0], y = raw[c & 1][t][1];
            float dx = raw[c & 1][t][3], dy = raw[c & 1][t][4];
            float4 v;
            v.x = __fsub_rn(x, __fmul_rn(0.5f, dx));
            v.y = __fsub_rn(y, __fmul_rn(0.5f, dy));
            v.z = __fadd_rn(x, __fmul_rn(0.5f, dx));
            v.w = __fadd_rn(y, __fmul_rn(0.5f, dy));
            bbChunk[t] = v;
            arChunk[t] = __fmul_rn(dx, dy);
        }
        __syncthreads();
        // (a) suppression of chunk boxes by global kept list (16 slots x 64 boxes)
        {
            int il = t & 63, ks = t >> 6;
            float4 bi = bbChunk[il]; float ai = arChunk[il];
            int kc = keptCount;
            bool sres = false;
            for (int kt = ks; kt < kc; kt += 16) {
                if (iou_sup(keptBB[kt], keptAr[kt], bi, ai)) { sres = true; break; }
            }
            if (sres) atomicOr(&supArr[il], 1u);
        }
        // (b) diagonal masks: diag[i] = bits j>i (within chunk) suppressed by i
        {
            int lane = t & 31;
#pragma unroll
            for (int pass = 0; pass < 4; pass++) {
                int i = pass * 16 + (t >> 6);
                int j = t & 63;
                bool p = false;
                if (j > i)
                    p = iou_sup(bbChunk[i], arChunk[i], bbChunk[j], arChunk[j]);
                u32 bal = __ballot_sync(0xFFFFFFFFu, p);
                if (lane == 0) diag32[i * 2 + ((t >> 5) & 1)] = bal;
            }
        }
        __syncthreads();
        if (t < 64) {
            u32 bal = __ballot_sync(0xFFFFFFFFu, supArr[t] != 0);
            if ((t & 31) == 0) ballots[t >> 5] = bal;
        }
        __syncthreads();
        // (c) serial greedy within chunk
        if (t == 0) {
            prevCount = keptCount;
            u64 live = ~(((u64)ballots[1] << 32) | (u64)ballots[0]);
            int kc = keptCount;
            for (int j = 0; j < 64 && kc < NPOST; j++) {
                if ((live >> j) & 1) {
                    keptIdx[kc++] = c * 64 + j;
                    u64 w = ((u64)diag32[j * 2 + 1] << 32) | (u64)diag32[j * 2];
                    live &= ~w;
                }
            }
            keptCount = kc;
        }
        __syncthreads();
        {   // append new kept boxes to compact list
            int r2 = prevCount + t;
            if (r2 < keptCount) {
                int slot = keptIdx[r2] & 63;
                keptBB[r2] = bbChunk[slot];
                keptAr[r2] = arChunk[slot];
            }
        }
        if (doPf) raw[(c + 1) & 1][pl][pcomp] = pf;
        __syncthreads();
        if (keptCount >= NPOST) break;
    }

    // ---- output ----
    float* rois = out;                               // [4,512,7]
    float* scor = out + BATCH * NPOST * 7;           // [4,512]
    float* labl = scor + BATCH * NPOST;              // [4,512]
    int kc = keptCount;
    for (int r = t; r < NPOST; r += 1024) {
        float bx[7] = {0, 0, 0, 0, 0, 0, 0};
        float sc = 0.0f, lb = 1.0f;                  // empty: label 0+1
        if (r < kc) {
            u64 key = s[keptIdx[r]];
            int n = (u32)key;
            u32 enc = ~(u32)(key >> 32);
            u32 sbits = (enc & 0x80000000u) ? (enc ^ 0x80000000u) : ~enc;
            sc = __uint_as_float(sbits);
            const float* bp = boxes + ((size_t)b * NPTS + n) * 7;
#pragma unroll
            for (int k = 0; k < 7; k++) bx[k] = bp[k];
            const float* cp = cls + ((size_t)b * NPTS + n) * 3;
            float c0 = cp[0], c1 = cp[1], c2 = cp[2];
            int l = 0; float m = c0;
            if (c1 > m) { m = c1; l = 1; }
            if (c2 > m) { l = 2; }
            lb = (float)(l + 1);
        }
        float* rp = rois + ((size_t)b * NPOST + r) * 7;
#pragma unroll
        for (int k = 0; k < 7; k++) rp[k] = bx[k];
        scor[b * NPOST + r] = sc;
        labl[b * NPOST + r] = lb;
    }
}

// ---------------- launch ----------------
extern "C" void kernel_launch(void* const* d_in, const int* in_sizes, int n_in,
                              void* d_out, int out_size) {
    const float* boxes = (const float*)d_in[0];
    const float* cls   = (const float*)d_in[1];
    float* out = (float*)d_out;

    // static (~30 KB) + dynamic (32 KB) smem exceeds the 48 KB default: opt in.
    cudaFuncSetAttribute(fused_kernel,
                         cudaFuncAttributeMaxDynamicSharedMemorySize, 65536);

    segsort_kernel<<<32, 1024>>>(cls);
    fused_kernel<<<BATCH, 1024, 4096 * sizeof(u64)>>>(boxes, cls, out);
}